// round 6
// baseline (speedup 1.0000x reference)
#include <cuda_runtime.h>
#include <cuda_fp16.h>
#include <cuda_bf16.h>

#define RES   256
#define RANK  12
#define OUTC  8

// Corner-quad records: per (plane,y,x) a 64B record {v00,v01,v10,v11} of
// fp16x8 projected features, border clamp baked in. 12 MB, L2-resident.
__device__ uint4 g_planes_q[3 * RES * RES * 4];

// ---------------------------------------------------------------------------
// Prolog: one block = 16x16 output tile. Project the 17x17 halo tile into
// smem ONCE per texel, then emit 256 quad records from smem.
// ---------------------------------------------------------------------------
__global__ void __launch_bounds__(256)
build_quads_kernel(const float* __restrict__ pxy,
                   const float* __restrict__ pxz,
                   const float* __restrict__ pyz,
                   const float* __restrict__ W)
{
    const int p = blockIdx.z;
    const float* __restrict__ src = (p == 0) ? pxy : ((p == 1) ? pxz : pyz);

    __shared__ float w[OUTC][RANK];
    __shared__ uint4 tile[17][17];

    int tid = threadIdx.x;
    if (tid < OUTC * RANK) {
        int o = tid / RANK, k = tid % RANK;
        w[o][k] = W[o * (3 * RANK) + p * RANK + k];
    }
    __syncthreads();

    int bx = blockIdx.x * 16;
    int by = blockIdx.y * 16;

    // project 289 halo texels (each thread: 1, plus 33 threads do a 2nd)
    for (int l = tid; l < 17 * 17; l += 256) {
        int dy = l / 17, dx = l % 17;
        int sx = min(bx + dx, RES - 1);
        int sy = min(by + dy, RES - 1);
        const float* in = src + (size_t)(sy * RES + sx) * RANK;
        float4 i0 = __ldg((const float4*)(in));
        float4 i1 = __ldg((const float4*)(in + 4));
        float4 i2 = __ldg((const float4*)(in + 8));
        float f[RANK] = { i0.x,i0.y,i0.z,i0.w, i1.x,i1.y,i1.z,i1.w,
                          i2.x,i2.y,i2.z,i2.w };
        float o[OUTC];
        #pragma unroll
        for (int c = 0; c < OUTC; c++) {
            float s = 0.f;
            #pragma unroll
            for (int k = 0; k < RANK; k++) s = fmaf(f[k], w[c][k], s);
            o[c] = s;
        }
        __half2 h0 = __floats2half2_rn(o[0], o[1]);
        __half2 h1 = __floats2half2_rn(o[2], o[3]);
        __half2 h2 = __floats2half2_rn(o[4], o[5]);
        __half2 h3 = __floats2half2_rn(o[6], o[7]);
        uint4 r;
        r.x = *(unsigned int*)&h0; r.y = *(unsigned int*)&h1;
        r.z = *(unsigned int*)&h2; r.w = *(unsigned int*)&h3;
        tile[dy][dx] = r;
    }
    __syncthreads();

    int dx = tid & 15, dy = tid >> 4;
    int texel = (by + dy) * RES + (bx + dx);
    uint4* dst = &g_planes_q[((size_t)((p << 16) | texel)) << 2];
    dst[0] = tile[dy    ][dx    ];
    dst[1] = tile[dy    ][dx + 1];
    dst[2] = tile[dy + 1][dx    ];
    dst[3] = tile[dy + 1][dx + 1];
}

// ---------------------------------------------------------------------------
// Main kernel: 4 lanes per 2 points; lane c = corner c of both points.
// Each plane sample = ONE LDG.128 into a 64B-aligned quad -> 1 wavefront.
// ---------------------------------------------------------------------------
#define INV255x128 (128.f / 255.f)

__device__ __forceinline__ void point_accum(float cx, float cy, float cz,
                                            float cbase,
                                            float sx, float ox,
                                            float sy, float oy,
                                            __half2 acc[4])
{
    // unnormalize + clamp via saturate (subsumes coord clip); fma-pipe only
    float tx = 255.f * __saturatef(fmaf(cx, INV255x128, 0.5f));
    float ty = 255.f * __saturatef(fmaf(cy, INV255x128, 0.5f));
    float tz = 255.f * __saturatef(fmaf(cz, INV255x128, 0.5f));
    float fx = floorf(tx), fy = floorf(ty), fz = floorf(tz);
    float wx = tx - fx, wy = ty - fy, wz = tz - fz;

    // lane-side weights
    float u_x = fmaf(sx, wx, ox);
    float u_y = fmaf(sx, wy, ox);
    float v_y = fmaf(sy, wy, oy);
    float v_z = fmaf(sy, wz, oy);

    __half2 w0 = __float2half2_rn(u_x * v_y);   // xy
    __half2 w1 = __float2half2_rn(u_x * v_z);   // xz
    __half2 w2 = __float2half2_rn(u_y * v_z);   // yz

    // offsets in fp32 (exact, < 2^24): idx = p*262144 + y*1024 + x*4 + c
    float f0 = fmaf(fy, 1024.f, fmaf(fx, 4.f, cbase));
    float f1 = fmaf(fz, 1024.f, fmaf(fx, 4.f, cbase + 262144.f));
    float f2 = fmaf(fz, 1024.f, fmaf(fy, 4.f, cbase + 524288.f));
    int o0 = __float2int_rz(f0);
    int o1 = __float2int_rz(f1);
    int o2 = __float2int_rz(f2);

    uint4 a = __ldg(&g_planes_q[o0]);
    uint4 b = __ldg(&g_planes_q[o1]);
    uint4 d = __ldg(&g_planes_q[o2]);

    acc[0] = __hfma2(*(__half2*)&a.x, w0, acc[0]);
    acc[1] = __hfma2(*(__half2*)&a.y, w0, acc[1]);
    acc[2] = __hfma2(*(__half2*)&a.z, w0, acc[2]);
    acc[3] = __hfma2(*(__half2*)&a.w, w0, acc[3]);
    acc[0] = __hfma2(*(__half2*)&b.x, w1, acc[0]);
    acc[1] = __hfma2(*(__half2*)&b.y, w1, acc[1]);
    acc[2] = __hfma2(*(__half2*)&b.z, w1, acc[2]);
    acc[3] = __hfma2(*(__half2*)&b.w, w1, acc[3]);
    acc[0] = __hfma2(*(__half2*)&d.x, w2, acc[0]);
    acc[1] = __hfma2(*(__half2*)&d.y, w2, acc[1]);
    acc[2] = __hfma2(*(__half2*)&d.z, w2, acc[2]);
    acc[3] = __hfma2(*(__half2*)&d.w, w2, acc[3]);
}

__device__ __forceinline__ __half2 hshfl(__half2 v, int lanemask) {
    unsigned int u = *(unsigned int*)&v;
    unsigned int s = __shfl_xor_sync(0xffffffffu, u, lanemask);
    return *(__half2*)&s;
}

__global__ void __launch_bounds__(256)
geo_encoder_kernel(const float* __restrict__ coords,
                   const float* __restrict__ proj_b,
                   float* __restrict__ out,
                   int N)
{
    int t = blockIdx.x * blockDim.x + threadIdx.x;
    int g = t >> 2;              // point-pair index (points 2g, 2g+1)
    int iA = 2 * g;
    if (iA >= N) return;
    int c = t & 3;               // corner: bit0 = x side, bit1 = y side
    bool hasB = (iA + 1) < N;

    // coords for both points: 2 lane-loads + 6 narrow shuffles
    size_t base = 6 * (size_t)g;
    float v0 = (c < 3 || hasB) ? __ldg(coords + base + c) : 0.f;
    float v1 = (c < 2 && hasB) ? __ldg(coords + base + 4 + c) : 0.f;
    float cxA = __shfl_sync(0xffffffffu, v0, 0, 4);
    float cyA = __shfl_sync(0xffffffffu, v0, 1, 4);
    float czA = __shfl_sync(0xffffffffu, v0, 2, 4);
    float cxB = __shfl_sync(0xffffffffu, v0, 3, 4);
    float cyB = __shfl_sync(0xffffffffu, v1, 0, 4);
    float czB = __shfl_sync(0xffffffffu, v1, 1, 4);

    float fxc = (float)(c & 1);
    float fyc = (float)(c >> 1);
    float sx = 2.f * fxc - 1.f, ox = 1.f - fxc;
    float sy = 2.f * fyc - 1.f, oy = 1.f - fyc;
    float cbase = (float)c;

    __half2 z = __float2half2_rn(0.f);
    __half2 accA[4] = { z, z, z, z };
    __half2 accB[4] = { z, z, z, z };

    point_accum(cxA, cyA, czA, cbase, sx, ox, sy, oy, accA);
    if (hasB) point_accum(cxB, cyB, czB, cbase, sx, ox, sy, oy, accB);

    // ── packed quad reduction: 6 SHFL total ──
    // Final layout: lane0=A ch0-3, lane1=A ch4-7, lane2=B ch0-3, lane3=B ch4-7.
    bool b0 = (c & 1) != 0;
    bool b1 = (c & 2) != 0;
    // low = dest regs of lanes with bit0=0 pattern {A0,A1,B0,B1}; high = {A2,A3,B2,B3}
    __half2 low[4]  = { accA[0], accA[1], accB[0], accB[1] };
    __half2 high[4] = { accA[2], accA[3], accB[2], accB[3] };
    __half2 r[4];
    #pragma unroll
    for (int k = 0; k < 4; k++) {
        __half2 keep = b0 ? high[k] : low[k];
        __half2 send = b0 ? low[k]  : high[k];
        r[k] = __hadd2(keep, hshfl(send, 1));
    }
    // round 2: lanes with bit1=0 keep A-part (r0,r1), send B-part (r2,r3)
    __half2 f[2];
    #pragma unroll
    for (int k = 0; k < 2; k++) {
        __half2 keep = b1 ? r[k + 2] : r[k];
        __half2 send = b1 ? r[k]     : r[k + 2];
        f[k] = __hadd2(keep, hshfl(send, 2));
    }

    float2 e0 = __half22float2(f[0]);
    float2 e1 = __half22float2(f[1]);

    float4 bias = __ldg((const float4*)proj_b + (c & 1));
    float o0 = fminf(fmaxf(e0.x + bias.x, -10.f), 10.f);
    float o1 = fminf(fmaxf(e0.y + bias.y, -10.f), 10.f);
    float o2 = fminf(fmaxf(e1.x + bias.z, -10.f), 10.f);
    float o3 = fminf(fmaxf(e1.y + bias.w, -10.f), 10.f);

    if (c < 2 || hasB)
        ((float4*)(out + 16 * (size_t)g))[c] = make_float4(o0, o1, o2, o3);
}

extern "C" void kernel_launch(void* const* d_in, const int* in_sizes, int n_in,
                              void* d_out, int out_size)
{
    const float* coords = (const float*)d_in[0];
    const float* pxy    = (const float*)d_in[1];
    const float* pxz    = (const float*)d_in[2];
    const float* pyz    = (const float*)d_in[3];
    const float* projw  = (const float*)d_in[4];
    const float* projb  = (const float*)d_in[5];
    float* out = (float*)d_out;

    int N = in_sizes[0] / 3;

    dim3 qgrid(RES / 16, RES / 16, 3);
    build_quads_kernel<<<qgrid, 256>>>(pxy, pxz, pyz, projw);

    long long pairs = (N + 1) / 2;
    long long threads = 4LL * pairs;
    int blocks = (int)((threads + 255) / 256);
    geo_encoder_kernel<<<blocks, 256>>>(coords, projb, out, N);
}

// round 7
// speedup vs baseline: 1.2519x; 1.2519x over previous
#include <cuda_runtime.h>
#include <cuda_fp16.h>
#include <cuda_bf16.h>

#define RES   256
#define RANK  12
#define OUTC  8

// Corner-quad records: per (plane,y,x) a 64B record {v00,v01,v10,v11} of
// fp16x8 projected features, border clamp baked in. 12 MB, L2-resident.
__device__ uint4 g_planes_q[3 * RES * RES * 4];

// ---------------------------------------------------------------------------
// Prolog (tiled): one block = 16x16 output tile. Project the 17x17 halo tile
// into smem ONCE per texel, then emit 256 quad records from smem.
// ---------------------------------------------------------------------------
__global__ void __launch_bounds__(256)
build_quads_kernel(const float* __restrict__ pxy,
                   const float* __restrict__ pxz,
                   const float* __restrict__ pyz,
                   const float* __restrict__ W)
{
    const int p = blockIdx.z;
    const float* __restrict__ src = (p == 0) ? pxy : ((p == 1) ? pxz : pyz);

    __shared__ float w[OUTC][RANK];
    __shared__ uint4 tile[17][17];

    int tid = threadIdx.x;
    if (tid < OUTC * RANK) {
        int o = tid / RANK, k = tid % RANK;
        w[o][k] = W[o * (3 * RANK) + p * RANK + k];
    }
    __syncthreads();

    int bx = blockIdx.x * 16;
    int by = blockIdx.y * 16;

    // project 289 halo texels (each thread: 1, plus 33 threads do a 2nd)
    for (int l = tid; l < 17 * 17; l += 256) {
        int dy = l / 17, dx = l % 17;
        int sx = min(bx + dx, RES - 1);
        int sy = min(by + dy, RES - 1);
        const float* in = src + (size_t)(sy * RES + sx) * RANK;
        float4 i0 = __ldg((const float4*)(in));
        float4 i1 = __ldg((const float4*)(in + 4));
        float4 i2 = __ldg((const float4*)(in + 8));
        float f[RANK] = { i0.x,i0.y,i0.z,i0.w, i1.x,i1.y,i1.z,i1.w,
                          i2.x,i2.y,i2.z,i2.w };
        float o[OUTC];
        #pragma unroll
        for (int c = 0; c < OUTC; c++) {
            float s = 0.f;
            #pragma unroll
            for (int k = 0; k < RANK; k++) s = fmaf(f[k], w[c][k], s);
            o[c] = s;
        }
        __half2 h0 = __floats2half2_rn(o[0], o[1]);
        __half2 h1 = __floats2half2_rn(o[2], o[3]);
        __half2 h2 = __floats2half2_rn(o[4], o[5]);
        __half2 h3 = __floats2half2_rn(o[6], o[7]);
        uint4 r;
        r.x = *(unsigned int*)&h0; r.y = *(unsigned int*)&h1;
        r.z = *(unsigned int*)&h2; r.w = *(unsigned int*)&h3;
        tile[dy][dx] = r;
    }
    __syncthreads();

    int dx = tid & 15, dy = tid >> 4;
    int texel = (by + dy) * RES + (bx + dx);
    uint4* dst = &g_planes_q[((size_t)((p << 16) | texel)) << 2];
    dst[0] = tile[dy    ][dx    ];
    dst[1] = tile[dy    ][dx + 1];
    dst[2] = tile[dy + 1][dx    ];
    dst[3] = tile[dy + 1][dx + 1];
}

// ---------------------------------------------------------------------------
// Main kernel (Round-5 proven version): 4 lanes per 2 points; lane c handles
// corner c of both points. Each plane sample = ONE LDG.128 into a 64B-aligned
// quad -> 1 wavefront per plane per point.
// ---------------------------------------------------------------------------
__device__ __forceinline__ void point_accum(float cx, float cy, float cz,
                                            int c, float sx, float ox,
                                            float sy, float oy,
                                            __half2 acc[4])
{
    // per-coordinate transform, once (subsumes coord clip)
    float tx = fminf(fmaxf(fmaf(cx, 128.f, 127.5f), 0.f), 255.f);
    float ty = fminf(fmaxf(fmaf(cy, 128.f, 127.5f), 0.f), 255.f);
    float tz = fminf(fmaxf(fmaf(cz, 128.f, 127.5f), 0.f), 255.f);
    float fx = floorf(tx), fy = floorf(ty), fz = floorf(tz);
    float wx = tx - fx, wy = ty - fy, wz = tz - fz;
    int x0 = (int)fx, y0 = (int)fy, z0 = (int)fz;

    // lane-side weights: first-axis uses corner bit0 (sx,ox), second-axis bit1
    float u_x = fmaf(sx, wx, ox);   // x as first axis (planes xy, xz)
    float u_y = fmaf(sx, wy, ox);   // y as first axis (plane yz)
    float v_y = fmaf(sy, wy, oy);   // y as second axis (plane xy)
    float v_z = fmaf(sy, wz, oy);   // z as second axis (planes xz, yz)

    __half2 w0 = __float2half2_rn(u_x * v_y);
    __half2 w1 = __float2half2_rn(u_x * v_z);
    __half2 w2 = __float2half2_rn(u_y * v_z);

    int o0 = ((          (y0 << 8) | x0) << 2) + c;
    int o1 = (((1 << 16) | (z0 << 8) | x0) << 2) + c;
    int o2 = (((2 << 16) | (z0 << 8) | y0) << 2) + c;

    uint4 a = __ldg(&g_planes_q[o0]);
    uint4 b = __ldg(&g_planes_q[o1]);
    uint4 d = __ldg(&g_planes_q[o2]);

    acc[0] = __hfma2(*(__half2*)&a.x, w0, acc[0]);
    acc[1] = __hfma2(*(__half2*)&a.y, w0, acc[1]);
    acc[2] = __hfma2(*(__half2*)&a.z, w0, acc[2]);
    acc[3] = __hfma2(*(__half2*)&a.w, w0, acc[3]);
    acc[0] = __hfma2(*(__half2*)&b.x, w1, acc[0]);
    acc[1] = __hfma2(*(__half2*)&b.y, w1, acc[1]);
    acc[2] = __hfma2(*(__half2*)&b.z, w1, acc[2]);
    acc[3] = __hfma2(*(__half2*)&b.w, w1, acc[3]);
    acc[0] = __hfma2(*(__half2*)&d.x, w2, acc[0]);
    acc[1] = __hfma2(*(__half2*)&d.y, w2, acc[1]);
    acc[2] = __hfma2(*(__half2*)&d.z, w2, acc[2]);
    acc[3] = __hfma2(*(__half2*)&d.w, w2, acc[3]);
}

__device__ __forceinline__ __half2 hshfl_add(__half2 v, int lanemask) {
    unsigned int u = *(unsigned int*)&v;
    unsigned int s = __shfl_xor_sync(0xffffffffu, u, lanemask);
    return __hadd2(v, *(__half2*)&s);
}

__global__ void __launch_bounds__(256)
geo_encoder_kernel(const float* __restrict__ coords,
                   const float* __restrict__ proj_b,
                   float* __restrict__ out,
                   int N)
{
    int t = blockIdx.x * blockDim.x + threadIdx.x;
    int g = t >> 2;              // point-pair index (points 2g, 2g+1)
    int iA = 2 * g;
    if (iA >= N) return;
    int c = t & 3;               // corner: bit0 = x side, bit1 = y side
    bool hasB = (iA + 1) < N;

    // coords for both points: 6 floats via 2 lane-loads + 6 narrow shuffles
    size_t base = 6 * (size_t)g;
    float v0 = (c < 3 || hasB) ? __ldg(coords + base + c) : 0.f;
    float v1 = (c < 2 && hasB) ? __ldg(coords + base + 4 + c) : 0.f;
    float cxA = __shfl_sync(0xffffffffu, v0, 0, 4);
    float cyA = __shfl_sync(0xffffffffu, v0, 1, 4);
    float czA = __shfl_sync(0xffffffffu, v0, 2, 4);
    float cxB = __shfl_sync(0xffffffffu, v0, 3, 4);
    float cyB = __shfl_sync(0xffffffffu, v1, 0, 4);
    float czB = __shfl_sync(0xffffffffu, v1, 1, 4);

    float fxc = (float)(c & 1);
    float fyc = (float)(c >> 1);
    float sx = 2.f * fxc - 1.f, ox = 1.f - fxc;
    float sy = 2.f * fyc - 1.f, oy = 1.f - fyc;

    __half2 z = __float2half2_rn(0.f);
    __half2 accA[4] = { z, z, z, z };
    __half2 accB[4] = { z, z, z, z };

    point_accum(cxA, cyA, czA, c, sx, ox, sy, oy, accA);
    if (hasB) point_accum(cxB, cyB, czB, c, sx, ox, sy, oy, accB);

    // quad butterfly reduction in half2 (8 shfl+hadd2 per point)
    #pragma unroll
    for (int r = 0; r < 4; r++) {
        accA[r] = hshfl_add(accA[r], 1);
        accA[r] = hshfl_add(accA[r], 2);
        accB[r] = hshfl_add(accB[r], 1);
        accB[r] = hshfl_add(accB[r], 2);
    }

    // lane c writes float4 #c of the pair's 64B output record:
    // c=0: ptA ch0-3, c=1: ptA ch4-7, c=2: ptB ch0-3, c=3: ptB ch4-7
    __half2 s0 = (c & 2) ? accB[(c & 1) * 2]     : accA[(c & 1) * 2];
    __half2 s1 = (c & 2) ? accB[(c & 1) * 2 + 1] : accA[(c & 1) * 2 + 1];
    float2 f0 = __half22float2(s0);
    float2 f1 = __half22float2(s1);

    float4 bias = __ldg((const float4*)proj_b + (c & 1));
    float o0 = fminf(fmaxf(f0.x + bias.x, -10.f), 10.f);
    float o1 = fminf(fmaxf(f0.y + bias.y, -10.f), 10.f);
    float o2 = fminf(fmaxf(f1.x + bias.z, -10.f), 10.f);
    float o3 = fminf(fmaxf(f1.y + bias.w, -10.f), 10.f);

    if (c < 2 || hasB)
        ((float4*)(out + 16 * (size_t)g))[c] = make_float4(o0, o1, o2, o3);
}

extern "C" void kernel_launch(void* const* d_in, const int* in_sizes, int n_in,
                              void* d_out, int out_size)
{
    const float* coords = (const float*)d_in[0];
    const float* pxy    = (const float*)d_in[1];
    const float* pxz    = (const float*)d_in[2];
    const float* pyz    = (const float*)d_in[3];
    const float* projw  = (const float*)d_in[4];
    const float* projb  = (const float*)d_in[5];
    float* out = (float*)d_out;

    int N = in_sizes[0] / 3;

    dim3 qgrid(RES / 16, RES / 16, 3);
    build_quads_kernel<<<qgrid, 256>>>(pxy, pxz, pyz, projw);

    long long pairs = (N + 1) / 2;
    long long threads = 4LL * pairs;
    int blocks = (int)((threads + 255) / 256);
    geo_encoder_kernel<<<blocks, 256>>>(coords, projb, out, N);
}